// round 3
// baseline (speedup 1.0000x reference)
#include <cuda_runtime.h>

// bi_LSTM_47218870453093
//
// Output = softmax over a length-1 axis == exactly 1.0f for every element,
// independent of all inputs (established R1, rel_err == 0.0 exactly).
// R1/R2 established the time is a fixed single-launch graph-replay floor
// (~4.6-4.7us); the 16KB of stores is ~100ns of real work. This round:
// absolute-minimal kernel body — one float4 store per thread, no loops,
// no predicates on the fast path, grid sized exactly (4 blocks x 256 thr
// = 1024 float4 = 4096 floats).

__global__ __launch_bounds__(256, 1) void fill_ones_1store(float4* __restrict__ out) {
    out[blockIdx.x * 256 + threadIdx.x] =
        make_float4(1.0f, 1.0f, 1.0f, 1.0f);
}

// Generic fallback (defensive; out_size is 4096 for this problem).
__global__ void fill_ones_generic(float* __restrict__ out, int n) {
    int i = blockIdx.x * blockDim.x + threadIdx.x;
    if (i < n) out[i] = 1.0f;
}

extern "C" void kernel_launch(void* const* d_in, const int* in_sizes, int n_in,
                              void* d_out, int out_size) {
    (void)d_in; (void)in_sizes; (void)n_in;
    if (out_size == 4096) {
        // 4096 floats = 1024 float4; 4 blocks x 256 threads, 1 store each.
        fill_ones_1store<<<4, 256>>>(reinterpret_cast<float4*>(d_out));
    } else {
        int threads = 256;
        int blocks = (out_size + threads - 1) / threads;
        if (blocks < 1) blocks = 1;
        fill_ones_generic<<<blocks, threads>>>(reinterpret_cast<float*>(d_out), out_size);
    }
}

// round 4
// speedup vs baseline: 1.1014x; 1.1014x over previous
#include <cuda_runtime.h>

// bi_LSTM_47218870453093 — FINAL
//
// Output = softmax over a length-1 axis == exactly 1.0f for every element,
// independent of all inputs (R1, rel_err == 0.0 exactly). The entire
// bidirectional LSTM is dead code w.r.t. the output.
//
// R1-R3 established the remaining time (~4.7 +/- 0.2 us e2e, ~3.3-3.6 us
// kernel) is the fixed single-graph-node launch/replay floor on sm_100a:
// insensitive to grid shape, body complexity, and the 16KB (~0.1us) of real
// store work. This is the best-measured configuration (grid=4 x 256, one
// predicate-free STG.128 per thread), frozen.

__global__ __launch_bounds__(256, 1) void fill_ones_1store(float4* __restrict__ out) {
    out[blockIdx.x * 256 + threadIdx.x] =
        make_float4(1.0f, 1.0f, 1.0f, 1.0f);
}

// Generic fallback (defensive; out_size is 4096 for this problem).
__global__ void fill_ones_generic(float* __restrict__ out, int n) {
    int i = blockIdx.x * blockDim.x + threadIdx.x;
    if (i < n) out[i] = 1.0f;
}

extern "C" void kernel_launch(void* const* d_in, const int* in_sizes, int n_in,
                              void* d_out, int out_size) {
    (void)d_in; (void)in_sizes; (void)n_in;
    if (out_size == 4096) {
        // 4096 floats = 1024 float4; 4 blocks x 256 threads, 1 store each.
        fill_ones_1store<<<4, 256>>>(reinterpret_cast<float4*>(d_out));
    } else {
        int threads = 256;
        int blocks = (out_size + threads - 1) / threads;
        if (blocks < 1) blocks = 1;
        fill_ones_generic<<<blocks, threads>>>(reinterpret_cast<float*>(d_out), out_size);
    }
}